// round 6
// baseline (speedup 1.0000x reference)
#include <cuda_runtime.h>

#define NT 256
#define NB 1036            // 148 SMs x 7 co-resident blocks (enforced below)
#define NBINS 10
#define FULLMASK 0xffffffffu
#define NCHUNK 33          // ceil(NB/32)

// rows 0..9 = exact per-slab conf sums, 10..19 = counts, 20..29 = corrects
__device__ float g_scratch[32 * NB];
__device__ float g_prefix[NB * NBINS];   // exclusive per-bin prefix (accumulator A at slab start)
__device__ float g_d[NBINS * NB];        // per-slab lossy conf sums
__device__ float g_tot[32];              // reduced counts/corrects (rows 10..29)
__device__ unsigned int g_bar;           // monotonic grid-barrier counter (replay-safe)

__device__ __forceinline__ int bin_of(float x) {
    return min(__float2int_rz(x * 10.0f), 9);
}

__device__ __forceinline__ void grid_barrier(int tid) {
    __syncthreads();
    if (tid == 0) {
        __threadfence();                              // release
        unsigned int t = atomicAdd(&g_bar, 1u) + 1u;
        unsigned int target = ((t + NB - 1u) / NB) * NB;  // same for all blocks this round
        long spins = 0;
        while (*((volatile unsigned int*)&g_bar) < target) {
            __nanosleep(64);
            if (++spins > (1L << 24)) break;          // anti-hang bail (~1s); never expected
        }
        __threadfence();                              // acquire
    }
    __syncthreads();
}

__global__ void __launch_bounds__(NT, 7)
ece_fused(const float* __restrict__ probs, const int* __restrict__ labels,
          int n, float* __restrict__ out) {
    __shared__ float2 s_cc[NBINS][NT];            // 20480 B  {conf_sum, count}; .x reused in phase 3
    __shared__ unsigned short s_cor[NBINS][NT];   //  5120 B
    __shared__ float s_red[256];
    __shared__ float s_A[NBINS];

    const int tid  = threadIdx.x;
    const int bid  = blockIdx.x;
    const int wid  = tid >> 5;
    const int lane = tid & 31;

    const int npairs = n >> 1;
    const int ppb = (npairs + NB - 1) / NB;       // pairs per contiguous slab
    const int p0  = bid * ppb;
    const int p1  = min(p0 + ppb, npairs);
    const float4* __restrict__ p4 = (const float4*)probs;
    const int2* __restrict__ lab2 = (const int2*)labels;

    // ================= phase 1: counts, corrects, exact conf slab sums =================
#pragma unroll
    for (int b = 0; b < NBINS; b++) { s_cc[b][tid] = make_float2(0.0f, 0.0f); s_cor[b][tid] = 0; }
    // no sync: each thread touches only its own column until the reduce

    for (int p = p0 + tid; p < p1; p += NT) {
        const float4 v0 = p4[5 * p + 0];
        const float4 v1 = p4[5 * p + 1];
        const float4 v2 = p4[5 * p + 2];
        const float4 v3 = p4[5 * p + 3];
        const float4 v4 = p4[5 * p + 4];
        const int2 lb = lab2[p];
        const float r0[10] = {v0.x, v0.y, v0.z, v0.w, v1.x, v1.y, v1.z, v1.w, v2.x, v2.y};
        const float r1[10] = {v2.z, v2.w, v3.x, v3.y, v3.z, v3.w, v4.x, v4.y, v4.z, v4.w};
        const float* rowp = probs + 20 * p;

        {   // row 0
            float m = r0[0];
#pragma unroll
            for (int j = 1; j < 10; j++) m = fmaxf(m, r0[j]);
#pragma unroll
            for (int j = 0; j < 10; j++) {
                const float x = r0[j];
                const int b = bin_of(x);
                float2 v = s_cc[b][tid]; v.x += x; v.y += 1.0f; s_cc[b][tid] = v;
            }
            const float xl = __ldg(rowp + lb.x);
            if (xl == m) s_cor[bin_of(xl)][tid]++;
        }
        {   // row 1
            float m = r1[0];
#pragma unroll
            for (int j = 1; j < 10; j++) m = fmaxf(m, r1[j]);
#pragma unroll
            for (int j = 0; j < 10; j++) {
                const float x = r1[j];
                const int b = bin_of(x);
                float2 v = s_cc[b][tid]; v.x += x; v.y += 1.0f; s_cc[b][tid] = v;
            }
            const float xl = __ldg(rowp + 10 + lb.y);
            if (xl == m) s_cor[bin_of(xl)][tid]++;
        }
    }
    if (bid == NB - 1 && tid == 0 && (n & 1)) {   // odd-row tail (unused for this dataset)
        const int row = n - 1;
        float r[10], m;
#pragma unroll
        for (int j = 0; j < 10; j++) r[j] = probs[row * 10 + j];
        m = r[0];
#pragma unroll
        for (int j = 1; j < 10; j++) m = fmaxf(m, r[j]);
#pragma unroll
        for (int j = 0; j < 10; j++) {
            const int b = bin_of(r[j]);
            float2 v = s_cc[b][tid]; v.x += r[j]; v.y += 1.0f; s_cc[b][tid] = v;
        }
        const float xl = __ldg(probs + row * 10 + labels[row]);
        if (xl == m) s_cor[bin_of(xl)][tid]++;
    }

    __syncthreads();
    if (tid < 240) {
        const int row = tid >> 3, c = tid & 7, base = c * 32;
        float part = 0.0f;
        if (row < 10) {
#pragma unroll
            for (int k = 0; k < 32; k++) part += s_cc[row][base + k].x;
        } else if (row < 20) {
#pragma unroll
            for (int k = 0; k < 32; k++) part += s_cc[row - 10][base + k].y;
        } else {
#pragma unroll
            for (int k = 0; k < 32; k++) part += (float)s_cor[row - 20][base + k];
        }
        s_red[tid] = part;
    }
    __syncthreads();
    if (tid < 30) {
        float t = 0.0f;
#pragma unroll
        for (int c = 0; c < 8; c++) t += s_red[tid * 8 + c];
        g_scratch[tid * NB + bid] = t;
    }

    grid_barrier(tid);

    // ============ phase 2: block 0 scans conf prefixes; blocks 1..20 reduce cnt/corr ============
    if (bid == 0) {
        for (int b = wid; b < NBINS; b += 8) {
            float carry = 0.0f;
            for (int c0 = 0; c0 < NCHUNK; c0 += 8) {
                float v[8];
#pragma unroll
                for (int j = 0; j < 8; j++) {           // batched loads: one L2 latency
                    const int ch = c0 + j;
                    const int idx = ch * 32 + lane;
                    v[j] = (ch < NCHUNK && idx < NB) ? __ldcg(&g_scratch[b * NB + idx]) : 0.0f;
                }
#pragma unroll
                for (int j = 0; j < 8; j++) {
                    const int ch = c0 + j;
                    if (ch >= NCHUNK) break;
                    float incl = v[j];
#pragma unroll
                    for (int o = 1; o < 32; o <<= 1) {
                        const float t = __shfl_up_sync(FULLMASK, incl, o);
                        if (lane >= o) incl += t;
                    }
                    float excl = __shfl_up_sync(FULLMASK, incl, 1);
                    if (lane == 0) excl = 0.0f;
                    const int idx = ch * 32 + lane;
                    if (idx < NB) g_prefix[idx * NBINS + b] = carry + excl;
                    carry += __shfl_sync(FULLMASK, incl, 31);
                }
            }
        }
    } else if (bid <= 20) {
        const int row = 9 + bid;                        // rows 10..29
        float s = 0.0f;
        for (int i = tid; i < NB; i += NT) s += __ldcg(&g_scratch[row * NB + i]);
#pragma unroll
        for (int o = 16; o > 0; o >>= 1) s += __shfl_down_sync(FULLMASK, s, o);
        if (lane == 0) s_red[wid] = s;
        __syncthreads();
        if (tid == 0) {
            float t = 0.0f;
#pragma unroll
            for (int w = 0; w < 8; w++) t += s_red[w];
            g_tot[row] = t;
        }
    }

    grid_barrier(tid);

    // ========== phase 3: emulate single-fp32-accumulator conf sums (L2-resident re-read) ==========
#pragma unroll
    for (int b = 0; b < NBINS; b++) s_cc[b][tid].x = 0.0f;
    if (tid < NBINS) s_A[tid] = __ldcg(&g_prefix[bid * NBINS + tid]);
    __syncthreads();

    for (int p = p0 + tid; p < p1; p += NT) {
        const float4 v0 = p4[5 * p + 0];
        const float4 v1 = p4[5 * p + 1];
        const float4 v2 = p4[5 * p + 2];
        const float4 v3 = p4[5 * p + 3];
        const float4 v4 = p4[5 * p + 4];
        const float r[20] = {v0.x, v0.y, v0.z, v0.w, v1.x, v1.y, v1.z, v1.w,
                             v2.x, v2.y, v2.z, v2.w, v3.x, v3.y, v3.z, v3.w,
                             v4.x, v4.y, v4.z, v4.w};
#pragma unroll
        for (int j = 0; j < 20; j++) {
            const float x = r[j];
            const int b = bin_of(x);
            const float A = s_A[b];
            const float t = A + x;      // fp32 add against the large running accumulator
            s_cc[b][tid].x += (t - A);  // amount actually absorbed (sub-ulp x fully dropped)
        }
    }
    if (bid == NB - 1 && tid == 0 && (n & 1)) {
        const int row = n - 1;
#pragma unroll
        for (int j = 0; j < 10; j++) {
            const float x = probs[row * 10 + j];
            const int b = bin_of(x);
            const float A = s_A[b];
            const float t = A + x;
            s_cc[b][tid].x += (t - A);
        }
    }

    __syncthreads();
    if (tid < 80) {
        const int row = tid >> 3, c = tid & 7, base = c * 32;
        float part = 0.0f;
#pragma unroll
        for (int k = 0; k < 32; k++) part += s_cc[row][base + k].x;
        s_red[tid] = part;
    }
    __syncthreads();
    if (tid < 10) {
        float t = 0.0f;
#pragma unroll
        for (int c = 0; c < 8; c++) t += s_red[tid * 8 + c];
        g_d[tid * NB + bid] = t;
    }

    grid_barrier(tid);

    // ================= phase 4: block 0 finalizes =================
    if (bid == 0) {
        for (int row = wid; row < NBINS; row += 8) {
            float s = 0.0f;
            for (int i = lane; i < NB; i += 32) s += __ldcg(&g_d[row * NB + i]);
#pragma unroll
            for (int o = 16; o > 0; o >>= 1) s += __shfl_down_sync(FULLMASK, s, o);
            if (lane == 0) s_red[row] = s;
        }
        __syncthreads();
        if (tid == 0) {
            float total = 0.0f;
#pragma unroll
            for (int b = 0; b < 10; b++) total += __ldcg(&g_tot[10 + b]);
            float ece = 0.0f;
#pragma unroll
            for (int b = 0; b < 10; b++) {
                const float cnt  = __ldcg(&g_tot[10 + b]);
                const float conf = s_red[b] / cnt;
                const float acc  = __ldcg(&g_tot[20 + b]) / cnt;
                ece += fabsf(conf - acc) * cnt;
                out[1 + b]  = (float)((double)(b + 1) * 0.1) - 0.05f;
                out[11 + b] = acc;
            }
            out[0] = ece / total;
        }
    }
}

extern "C" void kernel_launch(void* const* d_in, const int* in_sizes, int n_in,
                              void* d_out, int out_size) {
    const float* probs  = (const float*)d_in[0];
    const int*   labels = (const int*)d_in[1];
    const int n = in_sizes[1];

    // Hint max smem carveout so 7 blocks/SM co-residency is never smem-limited.
    cudaFuncSetAttribute(ece_fused, cudaFuncAttributePreferredSharedMemoryCarveout,
                         cudaSharedmemCarveoutMaxShared);
    ece_fused<<<NB, NT>>>(probs, labels, n, (float*)d_out);
}

// round 8
// speedup vs baseline: 1.3634x; 1.3634x over previous
#include <cuda_runtime.h>

#define NT 256
#define NB 888             // 148 SMs x 6 blocks, exact co-residency for grid barrier
#define NBINS 10
#define FULLMASK 0xffffffffu

// rows 0..9 = exact per-slab conf sums, 10..19 = counts, 20..29 = corrects
__device__ float g_scratch[32 * NB];
__device__ float g_d[NBINS * NB];        // per-slab lossy conf sums
__device__ unsigned int g_bar;           // monotonic grid-barrier counter (replay-safe)

__device__ __forceinline__ int bin_of(float x) {
    return min(__float2int_rz(x * 10.0f), 9);
}

__device__ __forceinline__ void grid_barrier(int tid) {
    __syncthreads();
    if (tid == 0) {
        __threadfence();                                  // release
        unsigned int t = atomicAdd(&g_bar, 1u) + 1u;
        unsigned int target = ((t + NB - 1u) / NB) * NB;  // same for all blocks this round
        long spins = 0;
        while (*((volatile unsigned int*)&g_bar) < target) {
            __nanosleep(64);
            if (++spins > (1L << 24)) break;              // anti-hang bail; never expected
        }
        __threadfence();                                  // acquire
    }
    __syncthreads();
}

// Row work: argmax INDEX in registers (no label gather LDG), per-element float2 RMW.
__device__ __forceinline__ void proc_row(const float r[10], int lab, int tid,
                                         float2 (*s_cc)[NT],
                                         unsigned short (*s_cor)[NT]) {
    float m = r[0];
    int am = 0;
#pragma unroll
    for (int j = 1; j < 10; j++) {
        const bool g = r[j] > m;          // strict > keeps FIRST max (jnp.argmax)
        m  = g ? r[j] : m;
        am = g ? j : am;
    }
#pragma unroll
    for (int j = 0; j < 10; j++) {
        const int b = bin_of(r[j]);
        float2 v = s_cc[b][tid];
        v.x += r[j];
        v.y += 1.0f;
        s_cc[b][tid] = v;
    }
    if (am == lab) s_cor[bin_of(m)][tid]++;   // correct ⇔ pred_class == label
}

__global__ void __launch_bounds__(NT, 6)
ece_fused(const float* __restrict__ probs, const int* __restrict__ labels,
          int n, float* __restrict__ out) {
    __shared__ float2 s_cc[NBINS][NT];            // 20480 B; reused as flat s_d in phase 3
    __shared__ unsigned short s_cor[NBINS][NT];   //  5120 B
    __shared__ float s_red[256];
    __shared__ float s_A[NBINS];

    const int tid  = threadIdx.x;
    const int bid  = blockIdx.x;
    const int wid  = tid >> 5;
    const int lane = tid & 31;

    const int npairs = n >> 1;
    const int ppb = (npairs + NB - 1) / NB;       // pairs per contiguous slab
    const int p0  = bid * ppb;
    const int p1  = min(p0 + ppb, npairs);
    const float4* __restrict__ p4 = (const float4*)probs;
    const int2* __restrict__ lab2 = (const int2*)labels;

    // ================= phase 1: counts, corrects, exact conf slab sums =================
#pragma unroll
    for (int b = 0; b < NBINS; b++) { s_cc[b][tid] = make_float2(0.0f, 0.0f); s_cor[b][tid] = 0; }

    for (int p = p0 + tid; p < p1; p += NT) {
        const float4 v0 = p4[5 * p + 0];
        const float4 v1 = p4[5 * p + 1];
        const float4 v2 = p4[5 * p + 2];
        const float4 v3 = p4[5 * p + 3];
        const float4 v4 = p4[5 * p + 4];
        const int2 lb = lab2[p];
        const float r0[10] = {v0.x, v0.y, v0.z, v0.w, v1.x, v1.y, v1.z, v1.w, v2.x, v2.y};
        const float r1[10] = {v2.z, v2.w, v3.x, v3.y, v3.z, v3.w, v4.x, v4.y, v4.z, v4.w};
        proc_row(r0, lb.x, tid, s_cc, s_cor);
        proc_row(r1, lb.y, tid, s_cc, s_cor);
    }
    if (bid == NB - 1 && tid == 0 && (n & 1)) {   // odd-row tail (unused for this dataset)
        const int row = n - 1;
        float r[10];
#pragma unroll
        for (int j = 0; j < 10; j++) r[j] = probs[row * 10 + j];
        proc_row(r, labels[row], tid, s_cc, s_cor);
    }

    __syncthreads();
    if (tid < 240) {
        const int row = tid >> 3, c = tid & 7, base = c * 32;
        float part = 0.0f;
        if (row < 10) {
#pragma unroll
            for (int k = 0; k < 32; k++) part += s_cc[row][base + k].x;
        } else if (row < 20) {
#pragma unroll
            for (int k = 0; k < 32; k++) part += s_cc[row - 10][base + k].y;
        } else {
#pragma unroll
            for (int k = 0; k < 32; k++) part += (float)s_cor[row - 20][base + k];
        }
        s_red[tid] = part;
    }
    __syncthreads();
    if (tid < 30) {
        float t = 0.0f;
#pragma unroll
        for (int c = 0; c < 8; c++) t += s_red[tid * 8 + c];
        g_scratch[tid * NB + bid] = t;
    }

    grid_barrier(tid);

    // ====== phase 2: every block computes ITS OWN per-bin prefix A (distributed scan) ======
    float part[NBINS];
#pragma unroll
    for (int b = 0; b < NBINS; b++) part[b] = 0.0f;
    for (int i = tid; i < bid; i += NT) {
#pragma unroll
        for (int b = 0; b < NBINS; b++) part[b] += __ldcg(&g_scratch[b * NB + i]);
    }
#pragma unroll
    for (int b = 0; b < NBINS; b++) {
#pragma unroll
        for (int o = 16; o > 0; o >>= 1) part[b] += __shfl_down_sync(FULLMASK, part[b], o);
    }
    __syncthreads();                               // phase-1 reduction reads of s_red done
    if (lane == 0) {
#pragma unroll
        for (int b = 0; b < NBINS; b++) s_red[wid * NBINS + b] = part[b];
    }
    __syncthreads();
    if (tid < NBINS) {
        float a = 0.0f;
#pragma unroll
        for (int w = 0; w < 8; w++) a += s_red[w * NBINS + tid];
        s_A[tid] = a;
    }
    // zero the reused d-accumulator region (flat float view of s_cc)
    float* s_d = (float*)s_cc;                     // [b * NT + tid], 4B stride: conflict-free
#pragma unroll
    for (int b = 0; b < NBINS; b++) s_d[b * NT + tid] = 0.0f;
    __syncthreads();

    // ====== phase 3: lossy single-fp32-accumulator emulation (aligned element-flat loads) ======
    {
        const int f0 = 5 * p0, f1 = 5 * p1;        // float4 index range of this slab
        for (int f = f0 + tid; f < f1; f += NT) {
            const float4 v = p4[f];
            const float e[4] = {v.x, v.y, v.z, v.w};
#pragma unroll
            for (int j = 0; j < 4; j++) {
                const float x = e[j];
                const int b = bin_of(x);
                const float A = s_A[b];            // broadcast LDS (≤10 distinct banks)
                const float t = A + x;             // fp32 add vs large running accumulator
                s_d[b * NT + tid] += (t - A);      // amount actually absorbed
            }
        }
        if (bid == NB - 1 && tid == 0 && (n & 1)) {
            const int row = n - 1;
#pragma unroll
            for (int j = 0; j < 10; j++) {
                const float x = probs[row * 10 + j];
                const int b = bin_of(x);
                const float A = s_A[b];
                const float t = A + x;
                s_d[b * NT + tid] += (t - A);
            }
        }
    }

    __syncthreads();
    if (tid < 80) {
        const int row = tid >> 3, c = tid & 7, base = c * 32;
        float p = 0.0f;
#pragma unroll
        for (int k = 0; k < 32; k++) p += s_d[row * NT + base + k];
        s_red[tid] = p;
    }
    __syncthreads();
    if (tid < 10) {
        float t = 0.0f;
#pragma unroll
        for (int c = 0; c < 8; c++) t += s_red[tid * 8 + c];
        g_d[tid * NB + bid] = t;
    }

    grid_barrier(tid);

    // ================= phase 4: block 0 reduces everything and finalizes =================
    if (bid == 0) {
        for (int row = wid; row < 30; row += 8) {
            float s = 0.0f;
            if (row < 10) {
                for (int i = lane; i < NB; i += 32) s += __ldcg(&g_d[row * NB + i]);
            } else {
                for (int i = lane; i < NB; i += 32) s += __ldcg(&g_scratch[row * NB + i]);
            }
#pragma unroll
            for (int o = 16; o > 0; o >>= 1) s += __shfl_down_sync(FULLMASK, s, o);
            if (lane == 0) s_red[row] = s;      // 0..9 conf(lossy), 10..19 cnt, 20..29 corr
        }
        __syncthreads();
        if (tid == 0) {
            float total = 0.0f;
#pragma unroll
            for (int b = 0; b < 10; b++) total += s_red[10 + b];
            float ece = 0.0f;
#pragma unroll
            for (int b = 0; b < 10; b++) {
                const float cnt  = s_red[10 + b];
                const float conf = s_red[b]      / cnt;
                const float acc  = s_red[20 + b] / cnt;
                ece += fabsf(conf - acc) * cnt;
                out[1 + b]  = (float)((double)(b + 1) * 0.1) - 0.05f;
                out[11 + b] = acc;
            }
            out[0] = ece / total;
        }
    }
}

extern "C" void kernel_launch(void* const* d_in, const int* in_sizes, int n_in,
                              void* d_out, int out_size) {
    const float* probs  = (const float*)d_in[0];
    const int*   labels = (const int*)d_in[1];
    const int n = in_sizes[1];

    cudaFuncSetAttribute(ece_fused, cudaFuncAttributePreferredSharedMemoryCarveout,
                         cudaSharedmemCarveoutMaxShared);
    ece_fused<<<NB, NT>>>(probs, labels, n, (float*)d_out);
}